// round 6
// baseline (speedup 1.0000x reference)
#include <cuda_runtime.h>
#include <cuda_bf16.h>

static constexpr int UN = 2048;
static constexpr int TN = 512;
static constexpr int QN = 10000;
static constexpr int HN = 128;

// Scratch (__device__ globals: no allocation allowed in kernel_launch)
__device__ float4 g_trans[UN * TN];   // [t][u] : {lmda, mu, eps_ab, mask}
__device__ float2 g_AB[UN * TN];      // [t][u] : {A, B}
__device__ float  g_abT[UN * TN];     // [t][u] : ability (transposed)
__device__ float  g_muTab[2 * QN];
__device__ float  g_lmTab[2 * QN];
__device__ float  g_diffA[QN];
__device__ float  g_discA[QN];

__device__ __forceinline__ float gelu_exact(float x) {
    return 0.5f * x * (1.0f + erff(x * 0.70710678118654752f));
}

// ---------------------------------------------------------------------------
// Kernel 1: per-(question, resp) tables. 2*Q = 20000 rows through the MLP.
// W2 read via uniform-address __ldg float4 -> L1 broadcast across the warp.
// h1 kept fully in registers (128 regs), layer 3 fused into layer-2 j-loop.
// ---------------------------------------------------------------------------
__global__ void k_tables(const float* __restrict__ diff_mu, const float* __restrict__ diff_lv,
                         const float* __restrict__ disc_mu, const float* __restrict__ disc_lv,
                         const float* __restrict__ eps_diff, const float* __restrict__ eps_disc,
                         const float* __restrict__ W1, const float* __restrict__ b1,
                         const float* __restrict__ W2, const float* __restrict__ b2,
                         const float* __restrict__ W3, const float* __restrict__ b3)
{
    int i = blockIdx.x * blockDim.x + threadIdx.x;
    if (i >= 2 * QN) return;
    int q = i >> 1;
    float dif = diff_mu[q] + expf(0.5f * diff_lv[q]) * eps_diff[q];
    float dis = disc_mu[q] + expf(0.5f * disc_lv[q]) * eps_disc[q];
    if ((i & 1) == 0) { g_diffA[q] = dif; g_discA[q] = dis; }
    float x2 = (float)(i & 1);

    float h1[HN];
#pragma unroll
    for (int j = 0; j < HN; ++j) {
        float v = fmaf(dif, __ldg(&W1[j]),
                  fmaf(dis, __ldg(&W1[HN + j]),
                  fmaf(x2,  __ldg(&W1[2 * HN + j]), __ldg(&b1[j]))));
        h1[j] = gelu_exact(v);
    }

    float o0 = __ldg(&b3[0]);
    float o1 = __ldg(&b3[1]);
#pragma unroll 1
    for (int jg = 0; jg < HN; jg += 4) {
        float a0 = __ldg(&b2[jg + 0]);
        float a1 = __ldg(&b2[jg + 1]);
        float a2 = __ldg(&b2[jg + 2]);
        float a3 = __ldg(&b2[jg + 3]);
#pragma unroll
        for (int k = 0; k < HN; ++k) {
            float4 w = __ldg((const float4*)(W2 + k * HN + jg));
            a0 = fmaf(h1[k], w.x, a0);
            a1 = fmaf(h1[k], w.y, a1);
            a2 = fmaf(h1[k], w.z, a2);
            a3 = fmaf(h1[k], w.w, a3);
        }
        a0 = gelu_exact(a0);
        a1 = gelu_exact(a1);
        a2 = gelu_exact(a2);
        a3 = gelu_exact(a3);
        // W3 rows jg..jg+3, row-major (H,2): 8 consecutive floats
        float4 wa = __ldg((const float4*)(W3 + jg * 2));
        float4 wb = __ldg((const float4*)(W3 + jg * 2 + 4));
        o0 = fmaf(a0, wa.x, o0);  o1 = fmaf(a0, wa.y, o1);
        o0 = fmaf(a1, wa.z, o0);  o1 = fmaf(a1, wa.w, o1);
        o0 = fmaf(a2, wb.x, o0);  o1 = fmaf(a2, wb.y, o1);
        o0 = fmaf(a3, wb.z, o0);  o1 = fmaf(a3, wb.w, o1);
    }
    g_muTab[i] = o0;
    g_lmTab[i] = fminf(expf(-o1), 1e32f);
}

// ---------------------------------------------------------------------------
// Kernel 2: gather per-trial (lmda, mu, eps, mask) and transpose to (T,U)
// so the sequential scans are fully coalesced along U.
// ---------------------------------------------------------------------------
__global__ void k_gather(const int* __restrict__ mask, const int* __restrict__ q_id,
                         const float* __restrict__ resp, const float* __restrict__ eps_ab)
{
    __shared__ float4 tile[32][33];
    int t0 = blockIdx.x * 32, u0 = blockIdx.y * 32;
    int tx = threadIdx.x, ty = threadIdx.y;  // blockDim = (32, 8)
#pragma unroll
    for (int yy = 0; yy < 4; ++yy) {
        int u = u0 + ty + yy * 8;
        int t = t0 + tx;
        int gi = u * TN + t;
        int qq = __ldg(&q_id[gi]);
        float rv = __ldg(&resp[gi]);
        int idx = qq * 2 + (rv > 0.5f ? 1 : 0);
        tile[ty + yy * 8][tx] = make_float4(g_lmTab[idx], g_muTab[idx],
                                            __ldg(&eps_ab[gi]),
                                            __ldg(&mask[gi]) ? 1.0f : 0.0f);
    }
    __syncthreads();
#pragma unroll
    for (int yy = 0; yy < 4; ++yy) {
        int t = t0 + ty + yy * 8;
        int u = u0 + tx;
        g_trans[t * UN + u] = tile[tx][ty + yy * 8];
    }
}

// ---------------------------------------------------------------------------
// Kernel 3: fused backward + forward scan, one thread per user.
// Backward stores pre-update (A,B); forward consumes them immediately.
// ---------------------------------------------------------------------------
__global__ void k_scan()
{
    int u = blockIdx.x * blockDim.x + threadIdx.x;
    if (u >= UN) return;

    float a = 0.f, b = 0.f;
#pragma unroll 4
    for (int t = TN - 1; t >= 0; --t) {
        float4 v = g_trans[t * UN + u];
        g_AB[t * UN + u] = make_float2(a, b);
        if (v.w != 0.f) {
            float denom = v.x + a;                       // l + a*lth2 (lth2=1)
            float bn = (v.x * v.y + a * b) / denom;
            float an = denom / (1.f + denom);
            a = an;
            b = bn;
        }
    }

    float ab = 0.f;
#pragma unroll 4
    for (int t = 0; t < TN; ++t) {
        float4 v = g_trans[t * UN + u];
        float2 p = g_AB[t * UN + u];
        float denom = 1.f + v.x + p.x;                   // lth1 + l + an*lth1
        float mu_t = (ab + v.x * v.y + p.x * p.y) / denom;
        float std_t = sqrtf(1.f - p.x);
        if (v.w != 0.f) ab = mu_t + std_t * v.z;
        g_abT[t * UN + u] = ab;
    }
}

// ---------------------------------------------------------------------------
// Kernel 4: transpose ability back to (U,T), compute logits, write output.
// out = [trial_logits (U*T), trial_ability (U*T)]
// ---------------------------------------------------------------------------
__global__ void k_out(const int* __restrict__ q_id, float* __restrict__ out)
{
    __shared__ float tile[32][33];
    int t0 = blockIdx.x * 32, u0 = blockIdx.y * 32;
    int tx = threadIdx.x, ty = threadIdx.y;  // (32, 8)
#pragma unroll
    for (int yy = 0; yy < 4; ++yy) {
        int t = t0 + ty + yy * 8;
        tile[tx][ty + yy * 8] = g_abT[t * UN + u0 + tx];
    }
    __syncthreads();
    float* logits = out;
    float* abil = out + UN * TN;
#pragma unroll
    for (int yy = 0; yy < 4; ++yy) {
        int u = u0 + ty + yy * 8;
        int t = t0 + tx;
        int gi = u * TN + t;
        float ab = tile[ty + yy * 8][tx];
        int qq = __ldg(&q_id[gi]);
        abil[gi] = ab;
        logits[gi] = g_discA[qq] * (ab - g_diffA[qq]);
    }
}

extern "C" void kernel_launch(void* const* d_in, const int* in_sizes, int n_in,
                              void* d_out, int out_size)
{
    const int*   mask     = (const int*)d_in[0];
    const int*   q_id     = (const int*)d_in[1];
    const float* resp     = (const float*)d_in[2];
    const float* diff_mu  = (const float*)d_in[3];
    const float* diff_lv  = (const float*)d_in[4];
    const float* disc_mu  = (const float*)d_in[5];
    const float* disc_lv  = (const float*)d_in[6];
    const float* W1       = (const float*)d_in[7];
    const float* b1       = (const float*)d_in[8];
    const float* W2       = (const float*)d_in[9];
    const float* b2       = (const float*)d_in[10];
    const float* W3       = (const float*)d_in[11];
    const float* b3       = (const float*)d_in[12];
    const float* eps_diff = (const float*)d_in[13];
    const float* eps_disc = (const float*)d_in[14];
    const float* eps_ab   = (const float*)d_in[15];
    float* out = (float*)d_out;

    k_tables<<<(2 * QN + 127) / 128, 128>>>(diff_mu, diff_lv, disc_mu, disc_lv,
                                            eps_diff, eps_disc,
                                            W1, b1, W2, b2, W3, b3);
    dim3 tb(32, 8);
    dim3 gb(TN / 32, UN / 32);
    k_gather<<<gb, tb>>>(mask, q_id, resp, eps_ab);
    k_scan<<<UN / 256, 256>>>();
    k_out<<<gb, tb>>>(q_id, out);
}

// round 12
// speedup vs baseline: 1.2287x; 1.2287x over previous
#include <cuda_runtime.h>
#include <cuda_bf16.h>

static constexpr int UN = 2048;
static constexpr int TN = 512;
static constexpr int QN = 10000;
static constexpr int HN = 128;

// Scratch (__device__ globals: no allocation allowed in kernel_launch)
__device__ float4 g_trans[UN * TN];   // [t][u] : {lmda, lmda*mu, eps_ab, mask}
__device__ float2 g_AB[UN * TN];      // [t][u] : {A, B}
__device__ float  g_abT[UN * TN];     // [t][u] : ability (transposed)
__device__ float  g_muTab[2 * QN];
__device__ float  g_lmTab[2 * QN];
__device__ float  g_diffA[QN];
__device__ float  g_discA[QN];

__device__ __forceinline__ float gelu_exact(float x) {
    return 0.5f * x * (1.0f + erff(x * 0.70710678118654752f));
}

// ---------------------------------------------------------------------------
// Kernel 1: per-(question, resp) tables. 2*Q = 20000 rows through the MLP.
// ---------------------------------------------------------------------------
__global__ void k_tables(const float* __restrict__ diff_mu, const float* __restrict__ diff_lv,
                         const float* __restrict__ disc_mu, const float* __restrict__ disc_lv,
                         const float* __restrict__ eps_diff, const float* __restrict__ eps_disc,
                         const float* __restrict__ W1, const float* __restrict__ b1,
                         const float* __restrict__ W2, const float* __restrict__ b2,
                         const float* __restrict__ W3, const float* __restrict__ b3)
{
    int i = blockIdx.x * blockDim.x + threadIdx.x;
    if (i >= 2 * QN) return;
    int q = i >> 1;
    float dif = diff_mu[q] + expf(0.5f * diff_lv[q]) * eps_diff[q];
    float dis = disc_mu[q] + expf(0.5f * disc_lv[q]) * eps_disc[q];
    if ((i & 1) == 0) { g_diffA[q] = dif; g_discA[q] = dis; }
    float x2 = (float)(i & 1);

    float h1[HN];
#pragma unroll
    for (int j = 0; j < HN; ++j) {
        float v = fmaf(dif, __ldg(&W1[j]),
                  fmaf(dis, __ldg(&W1[HN + j]),
                  fmaf(x2,  __ldg(&W1[2 * HN + j]), __ldg(&b1[j]))));
        h1[j] = gelu_exact(v);
    }

    float o0 = __ldg(&b3[0]);
    float o1 = __ldg(&b3[1]);
#pragma unroll 1
    for (int jg = 0; jg < HN; jg += 4) {
        float a0 = __ldg(&b2[jg + 0]);
        float a1 = __ldg(&b2[jg + 1]);
        float a2 = __ldg(&b2[jg + 2]);
        float a3 = __ldg(&b2[jg + 3]);
#pragma unroll
        for (int k = 0; k < HN; ++k) {
            float4 w = __ldg((const float4*)(W2 + k * HN + jg));
            a0 = fmaf(h1[k], w.x, a0);
            a1 = fmaf(h1[k], w.y, a1);
            a2 = fmaf(h1[k], w.z, a2);
            a3 = fmaf(h1[k], w.w, a3);
        }
        a0 = gelu_exact(a0);
        a1 = gelu_exact(a1);
        a2 = gelu_exact(a2);
        a3 = gelu_exact(a3);
        float4 wa = __ldg((const float4*)(W3 + jg * 2));
        float4 wb = __ldg((const float4*)(W3 + jg * 2 + 4));
        o0 = fmaf(a0, wa.x, o0);  o1 = fmaf(a0, wa.y, o1);
        o0 = fmaf(a1, wa.z, o0);  o1 = fmaf(a1, wa.w, o1);
        o0 = fmaf(a2, wb.x, o0);  o1 = fmaf(a2, wb.y, o1);
        o0 = fmaf(a3, wb.z, o0);  o1 = fmaf(a3, wb.w, o1);
    }
    g_muTab[i] = o0;
    g_lmTab[i] = fminf(expf(-o1), 1e32f);
}

// ---------------------------------------------------------------------------
// Kernel 2: gather per-trial (lmda, lmda*mu, eps, mask), transpose to (T,U).
// ---------------------------------------------------------------------------
__global__ void k_gather(const int* __restrict__ mask, const int* __restrict__ q_id,
                         const float* __restrict__ resp, const float* __restrict__ eps_ab)
{
    __shared__ float4 tile[32][33];
    int t0 = blockIdx.x * 32, u0 = blockIdx.y * 32;
    int tx = threadIdx.x, ty = threadIdx.y;  // blockDim = (32, 8)
#pragma unroll
    for (int yy = 0; yy < 4; ++yy) {
        int u = u0 + ty + yy * 8;
        int t = t0 + tx;
        int gi = u * TN + t;
        int qq = __ldg(&q_id[gi]);
        float rv = __ldg(&resp[gi]);
        int idx = qq * 2 + (rv > 0.5f ? 1 : 0);
        float l = g_lmTab[idx];
        float lm = l * g_muTab[idx];
        tile[ty + yy * 8][tx] = make_float4(l, lm,
                                            __ldg(&eps_ab[gi]),
                                            __ldg(&mask[gi]) ? 1.0f : 0.0f);
    }
    __syncthreads();
#pragma unroll
    for (int yy = 0; yy < 4; ++yy) {
        int t = t0 + ty + yy * 8;
        int u = u0 + tx;
        g_trans[t * UN + u] = tile[tx][ty + yy * 8];
    }
}

// ---------------------------------------------------------------------------
// Kernel 3: fused backward + forward scan, one thread per user.
// Short-chain version: MUFU-rcp division (recurrences are contractions, so
// the ~2^-21 per-step error damps), forward reciprocal moved off-chain.
// ---------------------------------------------------------------------------
__global__ void k_scan()
{
    int u = blockIdx.x * blockDim.x + threadIdx.x;
    if (u >= UN) return;

    float a = 0.f, b = 0.f;
#pragma unroll 4
    for (int t = TN - 1; t >= 0; --t) {
        float4 v = g_trans[t * UN + u];
        g_AB[t * UN + u] = make_float2(a, b);
        float d  = v.x + a;                       // l + a      (chain: 4)
        float e  = d + 1.f;                       //            (chain: 4)
        float an = __fdividef(d, e);              // rcp+mul    (chain: ~20)
        float bn = __fdividef(fmaf(a, b, v.y), d);// off a-chain
        bool mk = v.w != 0.f;
        a = mk ? an : a;
        b = mk ? bn : b;
    }

    float ab = 0.f;
#pragma unroll 4
    for (int t = 0; t < TN; ++t) {
        float4 v = g_trans[t * UN + u];
        float2 p = g_AB[t * UN + u];
        float r2 = __fdividef(1.f, 1.f + v.x + p.x); // off ab-chain
        float c0 = fmaf(p.x, p.y, v.y);              // A*B + l*m (off-chain)
        float se = sqrtf(1.f - p.x) * v.z;           // off-chain
        float mu_t = (ab + c0) * r2;                 // chain: 4 + 4
        if (v.w != 0.f) ab = mu_t + se;              // chain: 4 + sel
        g_abT[t * UN + u] = ab;
    }
}

// ---------------------------------------------------------------------------
// Kernel 4: transpose ability back to (U,T), compute logits, write output.
// ---------------------------------------------------------------------------
__global__ void k_out(const int* __restrict__ q_id, float* __restrict__ out)
{
    __shared__ float tile[32][33];
    int t0 = blockIdx.x * 32, u0 = blockIdx.y * 32;
    int tx = threadIdx.x, ty = threadIdx.y;  // (32, 8)
#pragma unroll
    for (int yy = 0; yy < 4; ++yy) {
        int t = t0 + ty + yy * 8;
        tile[tx][ty + yy * 8] = g_abT[t * UN + u0 + tx];
    }
    __syncthreads();
    float* logits = out;
    float* abil = out + UN * TN;
#pragma unroll
    for (int yy = 0; yy < 4; ++yy) {
        int u = u0 + ty + yy * 8;
        int t = t0 + tx;
        int gi = u * TN + t;
        float ab = tile[ty + yy * 8][tx];
        int qq = __ldg(&q_id[gi]);
        abil[gi] = ab;
        logits[gi] = g_discA[qq] * (ab - g_diffA[qq]);
    }
}

extern "C" void kernel_launch(void* const* d_in, const int* in_sizes, int n_in,
                              void* d_out, int out_size)
{
    const int*   mask     = (const int*)d_in[0];
    const int*   q_id     = (const int*)d_in[1];
    const float* resp     = (const float*)d_in[2];
    const float* diff_mu  = (const float*)d_in[3];
    const float* diff_lv  = (const float*)d_in[4];
    const float* disc_mu  = (const float*)d_in[5];
    const float* disc_lv  = (const float*)d_in[6];
    const float* W1       = (const float*)d_in[7];
    const float* b1       = (const float*)d_in[8];
    const float* W2       = (const float*)d_in[9];
    const float* b2       = (const float*)d_in[10];
    const float* W3       = (const float*)d_in[11];
    const float* b3       = (const float*)d_in[12];
    const float* eps_diff = (const float*)d_in[13];
    const float* eps_disc = (const float*)d_in[14];
    const float* eps_ab   = (const float*)d_in[15];
    float* out = (float*)d_out;

    k_tables<<<(2 * QN + 127) / 128, 128>>>(diff_mu, diff_lv, disc_mu, disc_lv,
                                            eps_diff, eps_disc,
                                            W1, b1, W2, b2, W3, b3);
    dim3 tb(32, 8);
    dim3 gb(TN / 32, UN / 32);
    k_gather<<<gb, tb>>>(mask, q_id, resp, eps_ab);
    k_scan<<<UN / 256, 256>>>();
    k_out<<<gb, tb>>>(q_id, out);
}